// round 4
// baseline (speedup 1.0000x reference)
#include <cuda_runtime.h>
#include <cuda_fp16.h>
#include <cstdint>

#define NN 100000
#define EE 1600000
#define EPP 200000

// ---------------- scratch (static device globals; no allocation) ------------
__device__ int    g_deg[NN];
__device__ int    g_off[NN + 1];
__device__ int    g_cur[NN];
__device__ int    g_adj[EE];
__device__ float  g_dinv[NN];
__device__ __half g_hs1[(size_t)NN * 128];  // x@W1 (unscaled, fp16)
__device__ float  g_a1 [(size_t)NN * 128];  // aggregated layer-1 (pre-bias/relu)
__device__ __half g_hs2[(size_t)NN * 64];   // relu(a1+b1)@W2 (unscaled, fp16)
__device__ float  g_z  [(size_t)NN * 64];   // final embeddings (fp32)
__device__ int    g_bsum[256];
__device__ int    g_boff[256];
__device__ float  g_W1hi[128 * 128], g_W1lo[128 * 128];
__device__ float  g_W2hi[128 * 64],  g_W2lo[128 * 64];

// ---------------- tf32 helpers ----------------------------------------------
__device__ __forceinline__ uint32_t f2tf(float x) {
    uint32_t r;
    asm("cvt.rna.tf32.f32 %0, %1;" : "=r"(r) : "f"(x));
    return r;
}

__device__ __forceinline__ void mma8(float* c, const uint32_t* a, uint32_t b0, uint32_t b1) {
    asm("mma.sync.aligned.m16n8k8.row.col.f32.tf32.tf32.f32 "
        "{%0,%1,%2,%3}, {%4,%5,%6,%7}, {%8,%9}, {%0,%1,%2,%3};"
        : "+f"(c[0]), "+f"(c[1]), "+f"(c[2]), "+f"(c[3])
        : "r"(a[0]), "r"(a[1]), "r"(a[2]), "r"(a[3]), "r"(b0), "r"(b1));
}

// ---------------- degree / CSR build ----------------------------------------
__global__ void k_init_deg() {
    int i = blockIdx.x * blockDim.x + threadIdx.x;
    if (i < NN) g_deg[i] = 0;
}

__global__ void k_count(const int* __restrict__ dst) {
    int e = blockIdx.x * blockDim.x + threadIdx.x;
    if (e < EE) atomicAdd(&g_deg[dst[e]], 1);
}

__global__ void k_dinv() {
    int i = blockIdx.x * blockDim.x + threadIdx.x;
    if (i < NN) g_dinv[i] = rsqrtf((float)(g_deg[i] + 1));  // +1 self loop
}

__global__ void k_scan1() {
    __shared__ int s[512];
    int t = threadIdx.x;
    int idx = blockIdx.x * 512 + t;
    int v = (idx < NN) ? g_deg[idx] : 0;
    s[t] = v;
    __syncthreads();
#pragma unroll
    for (int o = 1; o < 512; o <<= 1) {
        int x = (t >= o) ? s[t - o] : 0;
        __syncthreads();
        s[t] += x;
        __syncthreads();
    }
    if (idx < NN) g_off[idx] = s[t] - v;
    if (t == 511) g_bsum[blockIdx.x] = s[511];
}

__global__ void k_scan2(int nb) {
    __shared__ int s[256];
    int t = threadIdx.x;
    int v = (t < nb) ? g_bsum[t] : 0;
    s[t] = v;
    __syncthreads();
#pragma unroll
    for (int o = 1; o < 256; o <<= 1) {
        int x = (t >= o) ? s[t - o] : 0;
        __syncthreads();
        s[t] += x;
        __syncthreads();
    }
    if (t < nb) g_boff[t] = s[t] - v;
}

__global__ void k_scan3() {
    int t = threadIdx.x;
    int idx = blockIdx.x * 512 + t;
    if (idx < NN) {
        int val = g_off[idx] + g_boff[blockIdx.x];
        g_off[idx] = val;
        g_cur[idx] = val;
        if (idx == 0) g_off[NN] = EE;
    }
}

__global__ void k_fill(const int* __restrict__ src, const int* __restrict__ dst) {
    int e = blockIdx.x * blockDim.x + threadIdx.x;
    if (e < EE) {
        int d = dst[e];
        int p = atomicAdd(&g_cur[d], 1);
        g_adj[p] = src[e];
    }
}

// ---------------- weight hi/lo split ----------------------------------------
__global__ void k_wprep(const float* __restrict__ W1, const float* __restrict__ W2) {
    int i = blockIdx.x * blockDim.x + threadIdx.x;
    if (i < 128 * 128) {
        float v = W1[i];
        uint32_t h = f2tf(v);
        g_W1hi[i] = __uint_as_float(h);
        g_W1lo[i] = __uint_as_float(f2tf(v - __uint_as_float(h)));
    } else if (i < 128 * 128 + 128 * 64) {
        int j = i - 128 * 128;
        float v = W2[j];
        uint32_t h = f2tf(v);
        g_W2hi[j] = __uint_as_float(h);
        g_W2lo[j] = __uint_as_float(f2tf(v - __uint_as_float(h)));
    }
}

// ---------------- tensor-core GEMM (3xTF32), fp16 output ---------------------
template<int LAYER>
__global__ __launch_bounds__(256) void k_tc(const float* __restrict__ Xsrc,
                                            const float* __restrict__ bias) {
    constexpr int MT   = (LAYER == 1) ? 128 : 256;
    constexpr int NOUT = (LAYER == 1) ? 128 : 64;
    constexpr int NP   = NOUT + 4;

    const float* Whi = (LAYER == 1) ? g_W1hi : g_W2hi;
    const float* Wlo = (LAYER == 1) ? g_W1lo : g_W2lo;
    const float* Xp  = (LAYER == 1) ? Xsrc : (const float*)g_a1;
    __half*      Out = (LAYER == 1) ? g_hs1 : g_hs2;

    __shared__ float Xs[MT * 20];     // 16 cols + pad 4
    __shared__ float Bh[16 * NP];
    __shared__ float Bl[16 * NP];

    const int tid  = threadIdx.x;
    const int lane = tid & 31;
    const int wid  = tid >> 5;
    const int g    = lane >> 2;
    const int t4   = lane & 3;
    const int row0 = blockIdx.x * MT;
    const int warpM = (LAYER == 1) ? (wid >> 1) * 32 : wid * 32;
    const int n0    = (LAYER == 1) ? (wid & 1) * 64 : 0;

    float acc[2][8][4];
#pragma unroll
    for (int mi = 0; mi < 2; mi++)
#pragma unroll
        for (int ni = 0; ni < 8; ni++)
#pragma unroll
            for (int q = 0; q < 4; q++) acc[mi][ni][q] = 0.f;

#pragma unroll 1
    for (int kc = 0; kc < 8; kc++) {
        const int kbase = kc * 16;
#pragma unroll
        for (int j = 0; j < MT / 64; j++) {
            int idx = tid + 256 * j;
            int r = idx >> 2, c4 = idx & 3;
            int gr = row0 + r;
            float4 v = {0.f, 0.f, 0.f, 0.f};
            if (gr < NN) {
                v = ((const float4*)(Xp + (size_t)gr * 128 + kbase))[c4];
                if (LAYER == 2) {
                    float4 bb = ((const float4*)(bias + kbase))[c4];
                    v.x = fmaxf(v.x + bb.x, 0.f);
                    v.y = fmaxf(v.y + bb.y, 0.f);
                    v.z = fmaxf(v.z + bb.z, 0.f);
                    v.w = fmaxf(v.w + bb.w, 0.f);
                }
            }
            *((float4*)(Xs + r * 20 + c4 * 4)) = v;
        }
#pragma unroll
        for (int j = 0; j < (16 * NOUT) / 1024; j++) {
            int idx = tid + 256 * j;
            int kk = idx / (NOUT / 4), c4 = idx % (NOUT / 4);
            float4 vh = ((const float4*)(Whi + (size_t)(kbase + kk) * NOUT))[c4];
            float4 vl = ((const float4*)(Wlo + (size_t)(kbase + kk) * NOUT))[c4];
            *((float4*)(Bh + kk * NP + c4 * 4)) = vh;
            *((float4*)(Bl + kk * NP + c4 * 4)) = vl;
        }
        __syncthreads();

#pragma unroll
        for (int ks = 0; ks < 2; ks++) {
            const int k0 = ks * 8;
            uint32_t ah[2][4], al[2][4];
#pragma unroll
            for (int mi = 0; mi < 2; mi++) {
                int rb = warpM + mi * 16;
                float x0 = Xs[(rb + g) * 20 + k0 + t4];
                float x1 = Xs[(rb + g + 8) * 20 + k0 + t4];
                float x2 = Xs[(rb + g) * 20 + k0 + t4 + 4];
                float x3 = Xs[(rb + g + 8) * 20 + k0 + t4 + 4];
                ah[mi][0] = f2tf(x0); al[mi][0] = f2tf(x0 - __uint_as_float(ah[mi][0]));
                ah[mi][1] = f2tf(x1); al[mi][1] = f2tf(x1 - __uint_as_float(ah[mi][1]));
                ah[mi][2] = f2tf(x2); al[mi][2] = f2tf(x2 - __uint_as_float(ah[mi][2]));
                ah[mi][3] = f2tf(x3); al[mi][3] = f2tf(x3 - __uint_as_float(ah[mi][3]));
            }
#pragma unroll
            for (int ni = 0; ni < 8; ni++) {
                int nn = n0 + ni * 8 + g;
                uint32_t bh0 = __float_as_uint(Bh[(k0 + t4) * NP + nn]);
                uint32_t bh1 = __float_as_uint(Bh[(k0 + t4 + 4) * NP + nn]);
                uint32_t bl0 = __float_as_uint(Bl[(k0 + t4) * NP + nn]);
                uint32_t bl1 = __float_as_uint(Bl[(k0 + t4 + 4) * NP + nn]);
#pragma unroll
                for (int mi = 0; mi < 2; mi++) {
                    mma8(acc[mi][ni], ah[mi], bh0, bh1);  // hi*hi
                    mma8(acc[mi][ni], al[mi], bh0, bh1);  // lo*hi
                    mma8(acc[mi][ni], ah[mi], bl0, bl1);  // hi*lo
                }
            }
        }
        __syncthreads();
    }

#pragma unroll
    for (int mi = 0; mi < 2; mi++) {
#pragma unroll
        for (int ni = 0; ni < 8; ni++) {
            int r  = row0 + warpM + mi * 16 + g;
            int cc = n0 + ni * 8 + 2 * t4;
            if (r < NN) {
                __half2 o = __floats2half2_rn(acc[mi][ni][0], acc[mi][ni][1]);
                *((__half2*)(Out + (size_t)r * NOUT + cc)) = o;
            }
            if (r + 8 < NN) {
                __half2 o = __floats2half2_rn(acc[mi][ni][2], acc[mi][ni][3]);
                *((__half2*)(Out + (size_t)(r + 8) * NOUT + cc)) = o;
            }
        }
    }
}

// ---------------- AGG 1 (4x pipelined): a1[d]=dd*(hs1[d]*dd + sum hs1[s]*ds) -
__global__ void k_agg1() {
    int gw = (blockIdx.x * blockDim.x + threadIdx.x) >> 5;
    if (gw >= NN) return;
    int lane = threadIdx.x & 31;
    int o0 = g_off[gw], o1 = g_off[gw + 1];
    const uint2* base = (const uint2*)g_hs1;
    float dd = g_dinv[gw];

    uint2 sv = base[(size_t)gw * 32 + lane];
    float2 p0 = __half22float2(*reinterpret_cast<const __half2*>(&sv.x));
    float2 p1 = __half22float2(*reinterpret_cast<const __half2*>(&sv.y));
    float a0 = p0.x * dd, a1 = p0.y * dd, a2 = p1.x * dd, a3 = p1.y * dd;

    int i = o0;
    for (; i + 4 <= o1; i += 4) {
        int s0 = g_adj[i], s1 = g_adj[i + 1], s2 = g_adj[i + 2], s3 = g_adj[i + 3];
        uint2 v0 = base[(size_t)s0 * 32 + lane];
        uint2 v1 = base[(size_t)s1 * 32 + lane];
        uint2 v2 = base[(size_t)s2 * 32 + lane];
        uint2 v3 = base[(size_t)s3 * 32 + lane];
        float d0 = g_dinv[s0], d1 = g_dinv[s1], d2 = g_dinv[s2], d3 = g_dinv[s3];
        float2 q;
        q = __half22float2(*reinterpret_cast<const __half2*>(&v0.x)); a0 += q.x * d0; a1 += q.y * d0;
        q = __half22float2(*reinterpret_cast<const __half2*>(&v0.y)); a2 += q.x * d0; a3 += q.y * d0;
        q = __half22float2(*reinterpret_cast<const __half2*>(&v1.x)); a0 += q.x * d1; a1 += q.y * d1;
        q = __half22float2(*reinterpret_cast<const __half2*>(&v1.y)); a2 += q.x * d1; a3 += q.y * d1;
        q = __half22float2(*reinterpret_cast<const __half2*>(&v2.x)); a0 += q.x * d2; a1 += q.y * d2;
        q = __half22float2(*reinterpret_cast<const __half2*>(&v2.y)); a2 += q.x * d2; a3 += q.y * d2;
        q = __half22float2(*reinterpret_cast<const __half2*>(&v3.x)); a0 += q.x * d3; a1 += q.y * d3;
        q = __half22float2(*reinterpret_cast<const __half2*>(&v3.y)); a2 += q.x * d3; a3 += q.y * d3;
    }
    for (; i < o1; i++) {
        int s = g_adj[i];
        float ds = g_dinv[s];
        uint2 v = base[(size_t)s * 32 + lane];
        float2 q0 = __half22float2(*reinterpret_cast<const __half2*>(&v.x));
        float2 q1 = __half22float2(*reinterpret_cast<const __half2*>(&v.y));
        a0 += q0.x * ds; a1 += q0.y * ds; a2 += q1.x * ds; a3 += q1.y * ds;
    }
    float4 o = {a0 * dd, a1 * dd, a2 * dd, a3 * dd};
    ((float4*)g_a1)[(size_t)gw * 32 + lane] = o;
}

// ---------------- AGG 2 (4x pipelined): z[d]=dd*(hs2[d]*dd + sum hs2[s]*ds)+b2
__global__ void k_agg2(const float* __restrict__ b2) {
    int gw = (blockIdx.x * blockDim.x + threadIdx.x) >> 5;
    if (gw >= NN) return;
    int lane = threadIdx.x & 31;
    int o0 = g_off[gw], o1 = g_off[gw + 1];
    const __half2* base = (const __half2*)g_hs2;
    float dd = g_dinv[gw];

    float2 p = __half22float2(base[(size_t)gw * 32 + lane]);
    float a0 = p.x * dd, a1 = p.y * dd;

    int i = o0;
    for (; i + 4 <= o1; i += 4) {
        int s0 = g_adj[i], s1 = g_adj[i + 1], s2 = g_adj[i + 2], s3 = g_adj[i + 3];
        __half2 h0 = base[(size_t)s0 * 32 + lane];
        __half2 h1 = base[(size_t)s1 * 32 + lane];
        __half2 h2 = base[(size_t)s2 * 32 + lane];
        __half2 h3 = base[(size_t)s3 * 32 + lane];
        float d0 = g_dinv[s0], d1 = g_dinv[s1], d2 = g_dinv[s2], d3 = g_dinv[s3];
        float2 q;
        q = __half22float2(h0); a0 += q.x * d0; a1 += q.y * d0;
        q = __half22float2(h1); a0 += q.x * d1; a1 += q.y * d1;
        q = __half22float2(h2); a0 += q.x * d2; a1 += q.y * d2;
        q = __half22float2(h3); a0 += q.x * d3; a1 += q.y * d3;
    }
    for (; i < o1; i++) {
        int s = g_adj[i];
        float ds = g_dinv[s];
        float2 v = __half22float2(base[(size_t)s * 32 + lane]);
        a0 += v.x * ds; a1 += v.y * ds;
    }
    float2 b = ((const float2*)b2)[lane];
    float2 o = {a0 * dd + b.x, a1 * dd + b.y};
    ((float2*)g_z)[(size_t)gw * 32 + lane] = o;
}

// ---------------- decode ------------------------------------------------------
__global__ void k_decode(const int* __restrict__ pos, const int* __restrict__ neg,
                         float* __restrict__ out) {
    int gw = (blockIdx.x * blockDim.x + threadIdx.x) >> 5;
    if (gw >= 2 * EPP) return;
    int lane = threadIdx.x & 31;
    int a, b;
    if (gw < EPP) { a = pos[gw];        b = pos[EPP + gw]; }
    else          { int j = gw - EPP; a = neg[j]; b = neg[EPP + j]; }
    const float2* Z = (const float2*)g_z;
    float2 za = Z[(size_t)a * 32 + lane];
    float2 zb = Z[(size_t)b * 32 + lane];
    float p = za.x * zb.x + za.y * zb.y;
#pragma unroll
    for (int o = 16; o > 0; o >>= 1) p += __shfl_xor_sync(0xFFFFFFFFu, p, o);
    if (lane == 0) out[gw] = p;
}

// ---------------- launch ------------------------------------------------------
extern "C" void kernel_launch(void* const* d_in, const int* in_sizes, int n_in,
                              void* d_out, int out_size) {
    const float* x   = (const float*)d_in[0];
    const int*   ei  = (const int*)  d_in[1];
    const int*   pos = (const int*)  d_in[2];
    const int*   neg = (const int*)  d_in[3];
    const float* W1  = (const float*)d_in[4];
    const float* b1  = (const float*)d_in[5];
    const float* W2  = (const float*)d_in[6];
    const float* b2  = (const float*)d_in[7];
    float* out = (float*)d_out;

    const int* src = ei;
    const int* dst = ei + EE;
    const int nb_scan = (NN + 511) / 512;  // 196

    static cudaStream_t s2 = nullptr;
    static cudaEvent_t ev0 = nullptr, ev1 = nullptr;
    if (!s2) {
        cudaStreamCreateWithFlags(&s2, cudaStreamNonBlocking);
        cudaEventCreateWithFlags(&ev0, cudaEventDisableTiming);
        cudaEventCreateWithFlags(&ev1, cudaEventDisableTiming);
    }

    // launches #1, #2 on main stream (so that k_tc<1> is host-launch #4 -> ncu)
    k_init_deg<<<(NN + 255) / 256, 256>>>();
    k_count<<<(EE + 255) / 256, 256>>>(dst);

    // fork: gemm1 (+ weight prep) has no CSR dependency
    cudaEventRecord(ev0, 0);
    cudaStreamWaitEvent(s2, ev0, 0);
    k_wprep<<<(128 * 128 + 128 * 64 + 255) / 256, 256, 0, s2>>>(W1, W2);  // #3
    k_tc<1><<<(NN + 127) / 128, 256, 0, s2>>>(x, nullptr);                 // #4 (profiled)
    cudaEventRecord(ev1, s2);

    // main stream: rest of CSR build (concurrent with gemm1)
    k_dinv<<<(NN + 255) / 256, 256>>>();
    k_scan1<<<nb_scan, 512>>>();
    k_scan2<<<1, 256>>>(nb_scan);
    k_scan3<<<nb_scan, 512>>>();
    k_fill<<<(EE + 255) / 256, 256>>>(src, dst);

    // join
    cudaStreamWaitEvent(0, ev1, 0);

    k_agg1<<<(NN * 32 + 255) / 256, 256>>>();
    k_tc<2><<<(NN + 255) / 256, 256>>>(nullptr, b1);
    k_agg2<<<(NN * 32 + 255) / 256, 256>>>(b2);
    k_decode<<<(2 * EPP * 32 + 255) / 256, 256>>>(pos, neg, out);
}

// round 5
// speedup vs baseline: 1.1120x; 1.1120x over previous
#include <cuda_runtime.h>
#include <cuda_fp16.h>
#include <cstdint>

#define NN 100000
#define EE 1600000
#define EPP 200000

// ---------------- scratch (static device globals; no allocation) ------------
__device__ int      g_deg[NN];
__device__ int      g_off[NN + 1];
__device__ int      g_cur[NN];
__device__ int      g_adj[EE];
__device__ float    g_dinv[NN];
__device__ __half   g_hs1[(size_t)NN * 128]; // x@W1 (unscaled, fp16)
__device__ float    g_a1 [(size_t)NN * 128]; // aggregated layer-1 (fp32)
__device__ __half   g_hs2[(size_t)NN * 64];  // relu(a1+b1)@W2 (unscaled, fp16)
__device__ __half   g_z  [(size_t)NN * 64];  // final embeddings (fp16)
__device__ int      g_bsum[256];
__device__ int      g_boff[256];
// packed weights: [n][k2] half2 = (W[2k2][n], W[2k2+1][n]), hi and lo parts
__device__ unsigned g_W1ph[128 * 64], g_W1pl[128 * 64];
__device__ unsigned g_W2ph[64 * 64],  g_W2pl[64 * 64];

// ---------------- fp16 helpers ----------------------------------------------
__device__ __forceinline__ unsigned f2h2(float a, float b) {
    __half2 h = __floats2half2_rn(a, b);
    return *reinterpret_cast<unsigned*>(&h);
}
__device__ __forceinline__ float2 h2f2(unsigned u) {
    __half2 h = *reinterpret_cast<__half2*>(&u);
    return __half22float2(h);
}

__device__ __forceinline__ void mmaf16(float* c, const unsigned* a, unsigned b0, unsigned b1) {
    asm("mma.sync.aligned.m16n8k16.row.col.f32.f16.f16.f32 "
        "{%0,%1,%2,%3}, {%4,%5,%6,%7}, {%8,%9}, {%0,%1,%2,%3};"
        : "+f"(c[0]), "+f"(c[1]), "+f"(c[2]), "+f"(c[3])
        : "r"(a[0]), "r"(a[1]), "r"(a[2]), "r"(a[3]), "r"(b0), "r"(b1));
}

// ---------------- degree / CSR build ----------------------------------------
__global__ void k_init_deg() {
    int i = blockIdx.x * blockDim.x + threadIdx.x;
    if (i < NN) g_deg[i] = 0;
}

__global__ void k_count(const int* __restrict__ dst) {
    int e = blockIdx.x * blockDim.x + threadIdx.x;
    if (e < EE) atomicAdd(&g_deg[dst[e]], 1);
}

__global__ void k_dinv() {
    int i = blockIdx.x * blockDim.x + threadIdx.x;
    if (i < NN) g_dinv[i] = rsqrtf((float)(g_deg[i] + 1));  // +1 self loop
}

__global__ void k_scan1() {
    __shared__ int s[512];
    int t = threadIdx.x;
    int idx = blockIdx.x * 512 + t;
    int v = (idx < NN) ? g_deg[idx] : 0;
    s[t] = v;
    __syncthreads();
#pragma unroll
    for (int o = 1; o < 512; o <<= 1) {
        int x = (t >= o) ? s[t - o] : 0;
        __syncthreads();
        s[t] += x;
        __syncthreads();
    }
    if (idx < NN) g_off[idx] = s[t] - v;
    if (t == 511) g_bsum[blockIdx.x] = s[511];
}

__global__ void k_scan2(int nb) {
    __shared__ int s[256];
    int t = threadIdx.x;
    int v = (t < nb) ? g_bsum[t] : 0;
    s[t] = v;
    __syncthreads();
#pragma unroll
    for (int o = 1; o < 256; o <<= 1) {
        int x = (t >= o) ? s[t - o] : 0;
        __syncthreads();
        s[t] += x;
        __syncthreads();
    }
    if (t < nb) g_boff[t] = s[t] - v;
}

__global__ void k_scan3() {
    int t = threadIdx.x;
    int idx = blockIdx.x * 512 + t;
    if (idx < NN) {
        int val = g_off[idx] + g_boff[blockIdx.x];
        g_off[idx] = val;
        g_cur[idx] = val;
        if (idx == 0) g_off[NN] = EE;
    }
}

__global__ void k_fill(const int* __restrict__ src, const int* __restrict__ dst) {
    int e = blockIdx.x * blockDim.x + threadIdx.x;
    if (e < EE) {
        int d = dst[e];
        int p = atomicAdd(&g_cur[d], 1);
        g_adj[p] = src[e];
    }
}

// ---------------- weight hi/lo split + transpose-pack ------------------------
// packed[n*64+k2] = half2(W[2k2][n], W[2k2+1][n]); lo = residual after fp16.
__global__ void k_wprep(const float* __restrict__ W1, const float* __restrict__ W2) {
    int i = blockIdx.x * blockDim.x + threadIdx.x;
    if (i < 128 * 64) {
        int n = i >> 6, k2 = i & 63;
        float w0 = W1[(2 * k2) * 128 + n];
        float w1 = W1[(2 * k2 + 1) * 128 + n];
        unsigned h = f2h2(w0, w1);
        float2 hf = h2f2(h);
        g_W1ph[i] = h;
        g_W1pl[i] = f2h2(w0 - hf.x, w1 - hf.y);
    } else if (i < 128 * 64 + 64 * 64) {
        int j = i - 128 * 64;
        int n = j >> 6, k2 = j & 63;
        float w0 = W2[(2 * k2) * 64 + n];
        float w1 = W2[(2 * k2 + 1) * 64 + n];
        unsigned h = f2h2(w0, w1);
        float2 hf = h2f2(h);
        g_W2ph[j] = h;
        g_W2pl[j] = f2h2(w0 - hf.x, w1 - hf.y);
    }
}

// ---------------- tensor-core GEMM: fp16 3-term split, m16n8k16 --------------
// LAYER 1: hs1[NN,128] = x @ W1          (MT=128, NOUT=128)
// LAYER 2: hs2[NN,64]  = relu(a1+b1)@W2  (MT=256, NOUT=64)
// block = 256 threads = 8 warps; warp tile 32x64; K=128 in 8 chunks of 16.
// smem rows padded to 12 words (8 used) -> conflict-free frag loads.
template<int LAYER>
__global__ __launch_bounds__(256) void k_tc(const float* __restrict__ Xsrc,
                                            const float* __restrict__ bias) {
    constexpr int MT   = (LAYER == 1) ? 128 : 256;
    constexpr int NOUT = (LAYER == 1) ? 128 : 64;

    const unsigned* Wph = (LAYER == 1) ? g_W1ph : g_W2ph;
    const unsigned* Wpl = (LAYER == 1) ? g_W1pl : g_W2pl;
    const float*    Xp  = (LAYER == 1) ? Xsrc : (const float*)g_a1;
    __half*         Out = (LAYER == 1) ? g_hs1 : g_hs2;

    __shared__ unsigned Ah[MT * 12], Al[MT * 12];
    __shared__ unsigned Bh[NOUT * 12], Bl[NOUT * 12];

    const int tid  = threadIdx.x;
    const int lane = tid & 31;
    const int wid  = tid >> 5;
    const int g    = lane >> 2;
    const int t4   = lane & 3;
    const int row0 = blockIdx.x * MT;
    const int warpM = (LAYER == 1) ? (wid >> 1) * 32 : wid * 32;
    const int n0    = (LAYER == 1) ? (wid & 1) * 64 : 0;

    float acc[2][8][4];
#pragma unroll
    for (int mi = 0; mi < 2; mi++)
#pragma unroll
        for (int ni = 0; ni < 8; ni++)
#pragma unroll
            for (int q = 0; q < 4; q++) acc[mi][ni][q] = 0.f;

#pragma unroll 1
    for (int kc = 0; kc < 8; kc++) {
        const int kbase = kc * 16;
        // ---- stage X chunk [MT x 16] fp32 -> hi/lo fp16 (bias+relu for L2) --
#pragma unroll
        for (int j = 0; j < MT / 64; j++) {
            int idx = tid + 256 * j;
            int r = idx >> 2, c4 = idx & 3;
            int gr = row0 + r;
            float4 v = {0.f, 0.f, 0.f, 0.f};
            if (gr < NN) {
                v = ((const float4*)(Xp + (size_t)gr * 128 + kbase))[c4];
                if (LAYER == 2) {
                    float4 bb = ((const float4*)(bias + kbase))[c4];
                    v.x = fmaxf(v.x + bb.x, 0.f);
                    v.y = fmaxf(v.y + bb.y, 0.f);
                    v.z = fmaxf(v.z + bb.z, 0.f);
                    v.w = fmaxf(v.w + bb.w, 0.f);
                }
            }
            unsigned h01 = f2h2(v.x, v.y), h23 = f2h2(v.z, v.w);
            float2 f01 = h2f2(h01), f23 = h2f2(h23);
            unsigned l01 = f2h2(v.x - f01.x, v.y - f01.y);
            unsigned l23 = f2h2(v.z - f23.x, v.w - f23.y);
            *(uint2*)&Ah[r * 12 + c4 * 2] = make_uint2(h01, h23);
            *(uint2*)&Al[r * 12 + c4 * 2] = make_uint2(l01, l23);
        }
        // ---- stage W chunk [NOUT x 8 half2] from prepacked global -----------
#pragma unroll
        for (int j = 0; j < NOUT / 64; j++) {
            int idx = tid + 256 * j;
            int n = idx >> 2, jp = (idx & 3) * 2;
            uint2 vh = *(const uint2*)&Wph[n * 64 + kc * 8 + jp];
            uint2 vl = *(const uint2*)&Wpl[n * 64 + kc * 8 + jp];
            *(uint2*)&Bh[n * 12 + jp] = vh;
            *(uint2*)&Bl[n * 12 + jp] = vl;
        }
        __syncthreads();

        // ---- A fragments (k16) for both m-tiles ------------------------------
        unsigned ah[2][4], al[2][4];
#pragma unroll
        for (int mi = 0; mi < 2; mi++) {
            int rbg = (warpM + mi * 16 + g) * 12;
            ah[mi][0] = Ah[rbg + t4];
            ah[mi][1] = Ah[rbg + 96 + t4];
            ah[mi][2] = Ah[rbg + t4 + 4];
            ah[mi][3] = Ah[rbg + 96 + t4 + 4];
            al[mi][0] = Al[rbg + t4];
            al[mi][1] = Al[rbg + 96 + t4];
            al[mi][2] = Al[rbg + t4 + 4];
            al[mi][3] = Al[rbg + 96 + t4 + 4];
        }
#pragma unroll
        for (int ni = 0; ni < 8; ni++) {
            int nb = (n0 + ni * 8 + g) * 12;
            unsigned bh0 = Bh[nb + t4], bh1 = Bh[nb + t4 + 4];
            unsigned bl0 = Bl[nb + t4], bl1 = Bl[nb + t4 + 4];
#pragma unroll
            for (int mi = 0; mi < 2; mi++) {
                mmaf16(acc[mi][ni], ah[mi], bh0, bh1);  // hi*hi
                mmaf16(acc[mi][ni], al[mi], bh0, bh1);  // lo*hi
                mmaf16(acc[mi][ni], ah[mi], bl0, bl1);  // hi*lo
            }
        }
        __syncthreads();
    }

    // ---- epilogue: fp16 output (dinv applied in aggregation) ----------------
#pragma unroll
    for (int mi = 0; mi < 2; mi++) {
#pragma unroll
        for (int ni = 0; ni < 8; ni++) {
            int r  = row0 + warpM + mi * 16 + g;
            int cc = n0 + ni * 8 + 2 * t4;
            if (r < NN) {
                __half2 o = __floats2half2_rn(acc[mi][ni][0], acc[mi][ni][1]);
                *((__half2*)(Out + (size_t)r * NOUT + cc)) = o;
            }
            if (r + 8 < NN) {
                __half2 o = __floats2half2_rn(acc[mi][ni][2], acc[mi][ni][3]);
                *((__half2*)(Out + (size_t)(r + 8) * NOUT + cc)) = o;
            }
        }
    }
}

// ---------------- AGG 1 (4x pipelined): a1[d]=dd*(hs1[d]*dd + sum hs1[s]*ds) -
__global__ void k_agg1() {
    int gw = (blockIdx.x * blockDim.x + threadIdx.x) >> 5;
    if (gw >= NN) return;
    int lane = threadIdx.x & 31;
    int o0 = g_off[gw], o1 = g_off[gw + 1];
    const uint2* base = (const uint2*)g_hs1;
    float dd = g_dinv[gw];

    uint2 sv = base[(size_t)gw * 32 + lane];
    float2 p0 = h2f2(sv.x), p1 = h2f2(sv.y);
    float a0 = p0.x * dd, a1 = p0.y * dd, a2 = p1.x * dd, a3 = p1.y * dd;

    int i = o0;
    for (; i + 4 <= o1; i += 4) {
        int s0 = g_adj[i], s1 = g_adj[i + 1], s2 = g_adj[i + 2], s3 = g_adj[i + 3];
        uint2 v0 = base[(size_t)s0 * 32 + lane];
        uint2 v1 = base[(size_t)s1 * 32 + lane];
        uint2 v2 = base[(size_t)s2 * 32 + lane];
        uint2 v3 = base[(size_t)s3 * 32 + lane];
        float d0 = g_dinv[s0], d1 = g_dinv[s1], d2 = g_dinv[s2], d3 = g_dinv[s3];
        float2 q;
        q = h2f2(v0.x); a0 += q.x * d0; a1 += q.y * d0;
        q = h2f2(v0.y); a2 += q.x * d0; a3 += q.y * d0;
        q = h2f2(v1.x); a0 += q.x * d1; a1 += q.y * d1;
        q = h2f2(v1.y); a2 += q.x * d1; a3 += q.y * d1;
        q = h2f2(v2.x); a0 += q.x * d2; a1 += q.y * d2;
        q = h2f2(v2.y); a2 += q.x * d2; a3 += q.y * d2;
        q = h2f2(v3.x); a0 += q.x * d3; a1 += q.y * d3;
        q = h2f2(v3.y); a2 += q.x * d3; a3 += q.y * d3;
    }
    for (; i < o1; i++) {
        int s = g_adj[i];
        float ds = g_dinv[s];
        uint2 v = base[(size_t)s * 32 + lane];
        float2 q0 = h2f2(v.x), q1 = h2f2(v.y);
        a0 += q0.x * ds; a1 += q0.y * ds; a2 += q1.x * ds; a3 += q1.y * ds;
    }
    float4 o = {a0 * dd, a1 * dd, a2 * dd, a3 * dd};
    ((float4*)g_a1)[(size_t)gw * 32 + lane] = o;
}

// ---------------- AGG 2: z[d]=dd*(hs2[d]*dd + sum hs2[s]*ds)+b2 (fp16 out) ---
__global__ void k_agg2(const float* __restrict__ b2) {
    int gw = (blockIdx.x * blockDim.x + threadIdx.x) >> 5;
    if (gw >= NN) return;
    int lane = threadIdx.x & 31;
    int o0 = g_off[gw], o1 = g_off[gw + 1];
    const __half2* base = (const __half2*)g_hs2;
    float dd = g_dinv[gw];

    float2 p = __half22float2(base[(size_t)gw * 32 + lane]);
    float a0 = p.x * dd, a1 = p.y * dd;

    int i = o0;
    for (; i + 4 <= o1; i += 4) {
        int s0 = g_adj[i], s1 = g_adj[i + 1], s2 = g_adj[i + 2], s3 = g_adj[i + 3];
        __half2 h0 = base[(size_t)s0 * 32 + lane];
        __half2 h1 = base[(size_t)s1 * 32 + lane];
        __half2 h2 = base[(size_t)s2 * 32 + lane];
        __half2 h3 = base[(size_t)s3 * 32 + lane];
        float d0 = g_dinv[s0], d1 = g_dinv[s1], d2 = g_dinv[s2], d3 = g_dinv[s3];
        float2 q;
        q = __half22float2(h0); a0 += q.x * d0; a1 += q.y * d0;
        q = __half22float2(h1); a0 += q.x * d1; a1 += q.y * d1;
        q = __half22float2(h2); a0 += q.x * d2; a1 += q.y * d2;
        q = __half22float2(h3); a0 += q.x * d3; a1 += q.y * d3;
    }
    for (; i < o1; i++) {
        int s = g_adj[i];
        float ds = g_dinv[s];
        float2 v = __half22float2(base[(size_t)s * 32 + lane]);
        a0 += v.x * ds; a1 += v.y * ds;
    }
    float2 b = ((const float2*)b2)[lane];
    __half2 oz = __floats2half2_rn(a0 * dd + b.x, a1 * dd + b.y);
    ((__half2*)g_z)[(size_t)gw * 32 + lane] = oz;
}

// ---------------- decode (fp16 z gather) -------------------------------------
__global__ void k_decode(const int* __restrict__ pos, const int* __restrict__ neg,
                         float* __restrict__ out) {
    int gw = (blockIdx.x * blockDim.x + threadIdx.x) >> 5;
    if (gw >= 2 * EPP) return;
    int lane = threadIdx.x & 31;
    int a, b;
    if (gw < EPP) { a = pos[gw];        b = pos[EPP + gw]; }
    else          { int j = gw - EPP; a = neg[j]; b = neg[EPP + j]; }
    const __half2* Z = (const __half2*)g_z;
    float2 za = __half22float2(Z[(size_t)a * 32 + lane]);
    float2 zb = __half22float2(Z[(size_t)b * 32 + lane]);
    float p = za.x * zb.x + za.y * zb.y;
#pragma unroll
    for (int o = 16; o > 0; o >>= 1) p += __shfl_xor_sync(0xFFFFFFFFu, p, o);
    if (lane == 0) out[gw] = p;
}

// ---------------- launch ------------------------------------------------------
extern "C" void kernel_launch(void* const* d_in, const int* in_sizes, int n_in,
                              void* d_out, int out_size) {
    const float* x   = (const float*)d_in[0];
    const int*   ei  = (const int*)  d_in[1];
    const int*   pos = (const int*)  d_in[2];
    const int*   neg = (const int*)  d_in[3];
    const float* W1  = (const float*)d_in[4];
    const float* b1  = (const float*)d_in[5];
    const float* W2  = (const float*)d_in[6];
    const float* b2  = (const float*)d_in[7];
    float* out = (float*)d_out;

    const int* src = ei;
    const int* dst = ei + EE;
    const int nb_scan = (NN + 511) / 512;  // 196

    static cudaStream_t s2 = nullptr;
    static cudaEvent_t ev0 = nullptr, ev1 = nullptr;
    if (!s2) {
        cudaStreamCreateWithFlags(&s2, cudaStreamNonBlocking);
        cudaEventCreateWithFlags(&ev0, cudaEventDisableTiming);
        cudaEventCreateWithFlags(&ev1, cudaEventDisableTiming);
    }

    // fork at the very start: gemm1 path overlaps the ENTIRE CSR build
    cudaEventRecord(ev0, 0);
    cudaStreamWaitEvent(s2, ev0, 0);

    k_init_deg<<<(NN + 255) / 256, 256>>>();                 // #1 main
    k_count<<<(EE + 255) / 256, 256>>>(dst);                 // #2 main
    k_wprep<<<48, 256, 0, s2>>>(W1, W2);                     // #3 s2
    k_tc<1><<<(NN + 127) / 128, 256, 0, s2>>>(x, nullptr);   // #4 s2 (profiled)
    cudaEventRecord(ev1, s2);

    k_dinv<<<(NN + 255) / 256, 256>>>();
    k_scan1<<<nb_scan, 512>>>();
    k_scan2<<<1, 256>>>(nb_scan);
    k_scan3<<<nb_scan, 512>>>();
    k_fill<<<(EE + 255) / 256, 256>>>(src, dst);

    // join
    cudaStreamWaitEvent(0, ev1, 0);

    k_agg1<<<(NN * 32 + 255) / 256, 256>>>();
    k_tc<2><<<(NN + 255) / 256, 256>>>(nullptr, b1);
    k_agg2<<<(NN * 32 + 255) / 256, 256>>>(b2);
    k_decode<<<(2 * EPP * 32 + 255) / 256, 256>>>(pos, neg, out);
}